// round 8
// baseline (speedup 1.0000x reference)
#include <cuda_runtime.h>
#include <cuda_fp16.h>
#include <math.h>
#include <stdint.h>

#define NN 50000
#define NE 640000
#define RR 8
#define DD 128
#define NRSEG (NN*RR)
#define NBLK ((NRSEG + 1023)/1024)

// ---------------- scratch (device globals; no allocations allowed) ----------
__device__ int    g_cnt[NRSEG];          // zero at load; self-zeroed by k_scatter
__device__ int    g_off[NRSEG];
__device__ int    g_cur[NRSEG];
__device__ unsigned long long g_tstat[NBLK];  // lookback flags; reset by k_scatter
__device__ int2   g_sd[NE];              // (src, dst) packed, CSR order
__device__ float  g_h[NN*DD];
__device__ __half g_W1h[(RR+1)*DD*DD];   // [chunk][n][k-permuted] half
__device__ __half g_W2h[(RR+1)*64*DD];

// k-permutation within each 16-group: slot order packs (2t,2t+1,2t+8,2t+9)
// adjacent so one LDS.64 yields both fp16-MMA fragments.
__device__ __forceinline__ int slot16(int c) {
    return ((c & 7) >> 1)*4 + (c & 1) + ((c & 8) >> 3)*2;
}

// ---------------- prelude: hist + weight cvt/permute fused -------------------
// seg ordering is RELATION-MAJOR: seg = rel*NN + node, so each (warp-rows, rel)
// owns one contiguous edge slice sorted by dst.
__global__ void k_pre(const int* __restrict__ dst, const int* __restrict__ typ,
                      const float* __restrict__ W1, const float* __restrict__ r1,
                      const float* __restrict__ W2, const float* __restrict__ r2) {
    const int HB = (NE + 255)/256;
    const int T1 = ((RR+1)*DD*DD + 255)/256;
    int b = blockIdx.x;
    if (b < HB) {
        int e = b*256 + threadIdx.x;
        if (e < NE) atomicAdd(&g_cnt[typ[e]*NN + dst[e]], 1);
    } else if (b < HB + T1) {
        int idx = (b - HB)*256 + threadIdx.x;
        if (idx < (RR+1)*DD*DD) {
            int chunk = idx / (DD*DD);
            int rem   = idx - chunk*(DD*DD);
            int n = rem >> 7, k = rem & 127;
            float v = (chunk < RR) ? W1[(size_t)chunk*DD*DD + (size_t)k*DD + n]
                                   : r1[(size_t)k*DD + n];
            g_W1h[(size_t)chunk*DD*DD + n*DD + (k & ~15) + slot16(k & 15)] =
                __float2half_rn(v);
        }
    } else {
        int idx = (b - HB - T1)*256 + threadIdx.x;
        if (idx < (RR+1)*64*DD) {
            int chunk = idx / (64*DD);
            int rem   = idx - chunk*(64*DD);
            int n = rem >> 7, k = rem & 127;
            float v = (chunk < RR) ? W2[(size_t)chunk*DD*64 + (size_t)k*64 + n]
                                   : r2[(size_t)k*64 + n];
            g_W2h[(size_t)chunk*64*DD + n*DD + (k & ~15) + slot16(k & 15)] =
                __float2half_rn(v);
        }
    }
}

// ---------------- single-pass decoupled-lookback scan ------------------------
// flag: [63:32]=state (0=invalid,1=aggregate,2=prefix), [31:0]=value
__global__ void __launch_bounds__(1024)
k_scan() {
    __shared__ int swarp[32];
    __shared__ int s_prefix;
    const int tid  = threadIdx.x;
    const int lane = tid & 31;
    const int wid  = tid >> 5;
    const int b    = blockIdx.x;
    const int i    = b*1024 + tid;

    int v = (i < NRSEG) ? g_cnt[i] : 0;

    // warp inclusive scan
    int x = v;
    #pragma unroll
    for (int d = 1; d < 32; d <<= 1) {
        int t = __shfl_up_sync(0xffffffffu, x, d);
        if (lane >= d) x += t;
    }
    if (lane == 31) swarp[wid] = x;
    __syncthreads();
    if (wid == 0) {
        int y = swarp[lane];
        #pragma unroll
        for (int d = 1; d < 32; d <<= 1) {
            int t = __shfl_up_sync(0xffffffffu, y, d);
            if (lane >= d) y += t;
        }
        swarp[lane] = y;
    }
    __syncthreads();
    int incl = x + ((wid > 0) ? swarp[wid-1] : 0);   // block-local inclusive
    int blocksum = swarp[31];

    if (tid == 0) {
        if (b == 0) {
            atomicExch(&g_tstat[0], (2ULL<<32) | (unsigned)blocksum);
            s_prefix = 0;
        } else {
            atomicExch(&g_tstat[b], (1ULL<<32) | (unsigned)blocksum);
            int run = 0;
            int j = b - 1;
            while (true) {
                unsigned long long f = atomicAdd(&g_tstat[j], 0ULL);
                unsigned st = (unsigned)(f >> 32);
                if (st == 0) { __nanosleep(40); continue; }
                run += (int)(unsigned)(f & 0xffffffffu);
                if (st == 2) break;
                --j;
            }
            atomicExch(&g_tstat[b], (2ULL<<32) | (unsigned)(run + blocksum));
            s_prefix = run;
        }
    }
    __syncthreads();
    if (i < NRSEG) {
        int o = s_prefix + incl - v;
        g_off[i] = o;
        g_cur[i] = o;
    }
}

__global__ void k_scatter(const int* __restrict__ src, const int* __restrict__ dst,
                          const int* __restrict__ typ) {
    int e = blockIdx.x*blockDim.x + threadIdx.x;
    if (e < NE) {
        int d = dst[e];
        int seg = typ[e]*NN + d;
        int pos = atomicAdd(&g_cur[seg], 1);
        g_sd[pos] = make_int2(src[e], d);
    }
    // self-clean for next graph replay (unread after this point)
    if (e < NRSEG) g_cnt[e] = 0;
    if (e < NBLK)  g_tstat[e] = 0ULL;
}

// ---------------- fused aggregate + GEMM layer (fp16 MMA) -------------------
__device__ __forceinline__ void mma_f16(float& c0, float& c1, float& c2, float& c3,
                                        uint32_t a0, uint32_t a1, uint32_t a2, uint32_t a3,
                                        uint32_t b0, uint32_t b1) {
    asm volatile(
        "mma.sync.aligned.m16n8k16.row.col.f32.f16.f16.f32 "
        "{%0,%1,%2,%3},{%4,%5,%6,%7},{%8,%9},{%0,%1,%2,%3};"
        : "+f"(c0), "+f"(c1), "+f"(c2), "+f"(c3)
        : "r"(a0), "r"(a1), "r"(a2), "r"(a3), "r"(b0), "r"(b1));
}

__device__ __forceinline__ uint32_t pack_h2(float x, float y) {
    __half2 h = __floats2half2_rn(x, y);
    return *reinterpret_cast<uint32_t*>(&h);
}
__device__ __forceinline__ float2 unpack_h2(uint32_t u) {
    __half2 h = *reinterpret_cast<__half2*>(&u);
    return __half22float2(h);
}

// CTA = 128 nodes, 256 threads, 8 warps; warp owns 16 rows (private sA slice).
// smem as half2 words, row pitch WP=68 (stride ≡ 4 banks mod 32 -> near
// conflict-free LDS.64 fragment loads). k-permuted layout: one uint2 load
// yields (a0,a2)/(a1,a3)/(b0,b1) fragment pairs for m16n8k16.
template<int O, bool SIG>
__global__ void __launch_bounds__(256, 2)
k_layer(const float* __restrict__ in,
        const __half* __restrict__ Wh,    // [9][O][DD] half, k-permuted
        const float* __restrict__ bias,
        float* __restrict__ out) {
    constexpr int TM = 128;
    constexpr int NT = 256;
    constexpr int WP = 68;     // half2 words per row (64 data + 4 pad)

    extern __shared__ uint32_t smem[];
    uint32_t* sA = smem;           // TM * WP
    uint32_t* sB = smem + TM*WP;   // O  * WP

    const int tid  = threadIdx.x;
    const int lane = tid & 31;
    const int wid  = tid >> 5;
    const int tile = blockIdx.x * TM;

    float acc[O/8][4];
    #pragma unroll
    for (int n8 = 0; n8 < O/8; ++n8) {
        acc[n8][0] = 0.f; acc[n8][1] = 0.f; acc[n8][2] = 0.f; acc[n8][3] = 0.f;
    }

    const int g  = lane >> 2;
    const int tg = lane & 3;
    const int rbase = wid * 16;    // warp's private row block
    // lane's two half2 store slots (natural cols 4l..4l+3 under permutation)
    const int wbase = (lane >> 2)*8 + ((lane & 1) << 2) + ((lane & 2) >> 1);

    for (int r = 0; r < RR + 1; ++r) {
        __syncthreads();   // prev chunk's MMA done reading sB
        // ---- fill sB: pure half2 copy (pre-permuted in k_pre)
        {
            const uint32_t* Wp = reinterpret_cast<const uint32_t*>(
                Wh + (size_t)r*O*DD);
            #pragma unroll 4
            for (int idx = tid; idx < O*DD/2; idx += NT) {
                int n = idx >> 6, kk = idx & 63;
                sB[n*WP + kk] = Wp[idx];
            }
        }
        __syncthreads();   // sB ready

        // ================= gather (warp-private rows; no CTA barrier) ========
        if (r < RR) {
            // zero warp's 16 rows (contiguous block of 16*WP words)
            for (int w = lane; w < 16*WP; w += 32) sA[rbase*WP + w] = 0u;

            // lane l (l<=16) holds boundary offset for row rbase+l
            int bidx = r*NN + min(tile + rbase + min(lane, 16), NN);
            int offv = (bidx < NRSEG) ? g_off[bidx] : NE;
            int es = __shfl_sync(0xffffffffu, offv, 0);
            int ee = __shfl_sync(0xffffffffu, offv, 16);

            // branch-free predicated run accumulate, unconditional overwrite STS
            float4 v = make_float4(0.f,0.f,0.f,0.f);
            int currow = -1;
            #pragma unroll 8
            for (int e = es; e < ee; ++e) {
                int2 sd = g_sd[e];                 // warp-uniform broadcast
                const float4 xv = *reinterpret_cast<const float4*>(
                    in + (size_t)sd.x*DD + (lane<<2));
                bool fresh = (sd.y != currow);
                currow = sd.y;
                v.x = (fresh ? 0.f : v.x) + xv.x;
                v.y = (fresh ? 0.f : v.y) + xv.y;
                v.z = (fresh ? 0.f : v.z) + xv.z;
                v.w = (fresh ? 0.f : v.w) + xv.w;
                int rw = (currow - tile)*WP;
                sA[rw + wbase]     = pack_h2(v.x, v.y);   // last write wins
                sA[rw + wbase + 2] = pack_h2(v.z, v.w);
            }

            // post-pass: scale rows by 1/cnt (thread-local slots)
            #pragma unroll
            for (int i = 0; i < 16; ++i) {
                int c = __shfl_sync(0xffffffffu, offv, i+1)
                      - __shfl_sync(0xffffffffu, offv, i);
                if (c > 0) {
                    float inv = 1.f/(float)c;
                    int idx = (rbase+i)*WP + wbase;
                    float2 u0 = unpack_h2(sA[idx]);
                    float2 u1 = unpack_h2(sA[idx+2]);
                    sA[idx]   = pack_h2(u0.x*inv, u0.y*inv);
                    sA[idx+2] = pack_h2(u1.x*inv, u1.y*inv);
                }
            }
        } else {
            // root chunk: direct copy of input tile
            #pragma unroll
            for (int ii = 0; ii < 16; ++ii) {
                int node = tile + rbase + ii;
                float4 xv = make_float4(0.f,0.f,0.f,0.f);
                if (node < NN)
                    xv = *reinterpret_cast<const float4*>(
                        in + (size_t)node*DD + (lane<<2));
                int idx = (rbase+ii)*WP + wbase;
                sA[idx]   = pack_h2(xv.x, xv.y);
                sA[idx+2] = pack_h2(xv.z, xv.w);
            }
        }
        __syncwarp();      // cross-lane sA reads in MMA below

        // ================= MMA (fp16, fp32 accum) =================
        #pragma unroll
        for (int k16 = 0; k16 < DD/16; ++k16) {
            const uint2 aLo = *reinterpret_cast<const uint2*>(
                &sA[(rbase + g    )*WP + k16*8 + tg*2]);   // (a0, a2)
            const uint2 aHi = *reinterpret_cast<const uint2*>(
                &sA[(rbase + g + 8)*WP + k16*8 + tg*2]);   // (a1, a3)
            #pragma unroll
            for (int n8 = 0; n8 < O/8; ++n8) {
                const uint2 bb = *reinterpret_cast<const uint2*>(
                    &sB[(n8*8 + g)*WP + k16*8 + tg*2]);    // (b0, b1)
                mma_f16(acc[n8][0], acc[n8][1], acc[n8][2], acc[n8][3],
                        aLo.x, aHi.x, aLo.y, aHi.y, bb.x, bb.y);
            }
        }
    }

    // ---- epilogue: bias (+ sigmoid), write out
    const int r0 = tile + rbase + g;
    const int r1 = r0 + 8;
    #pragma unroll
    for (int n8 = 0; n8 < O/8; ++n8) {
        int c0 = n8*8 + 2*tg;
        int c1 = c0 + 1;
        float bz0 = bias[c0], bz1 = bias[c1];
        float v00 = acc[n8][0] + bz0;
        float v01 = acc[n8][1] + bz1;
        float v10 = acc[n8][2] + bz0;
        float v11 = acc[n8][3] + bz1;
        if (SIG) {
            v00 = 1.f/(1.f + __expf(-v00));
            v01 = 1.f/(1.f + __expf(-v01));
            v10 = 1.f/(1.f + __expf(-v10));
            v11 = 1.f/(1.f + __expf(-v11));
        }
        if (r0 < NN) { out[(size_t)r0*O + c0] = v00; out[(size_t)r0*O + c1] = v01; }
        if (r1 < NN) { out[(size_t)r1*O + c0] = v10; out[(size_t)r1*O + c1] = v11; }
    }
}

// ---------------- launch ----------------------------------------------------
extern "C" void kernel_launch(void* const* d_in, const int* in_sizes, int n_in,
                              void* d_out, int out_size) {
    const float* x    = (const float*)d_in[0];
    const int*   esrc = (const int*)  d_in[1];
    const int*   edst = (const int*)  d_in[2];
    const int*   etyp = (const int*)  d_in[3];
    const float* W1   = (const float*)d_in[4];
    const float* r1   = (const float*)d_in[5];
    const float* b1   = (const float*)d_in[6];
    const float* W2   = (const float*)d_in[7];
    const float* r2   = (const float*)d_in[8];
    const float* b2   = (const float*)d_in[9];
    float* out = (float*)d_out;

    constexpr int SMEM_L1 = (128 + 128) * 68 * 4;  // 69632 B -> 2 CTAs/SM
    constexpr int SMEM_L2 = (128 +  64) * 68 * 4;  // 52224 B -> 2 CTAs/SM
    cudaFuncSetAttribute(k_layer<128,false>, cudaFuncAttributeMaxDynamicSharedMemorySize, SMEM_L1);
    cudaFuncSetAttribute(k_layer< 64,true >, cudaFuncAttributeMaxDynamicSharedMemorySize, SMEM_L2);

    void* p = nullptr;
    cudaGetSymbolAddress(&p, g_h);   float*  h   = (float*)p;
    cudaGetSymbolAddress(&p, g_W1h); __half* w1h = (__half*)p;
    cudaGetSymbolAddress(&p, g_W2h); __half* w2h = (__half*)p;

    const int HB = (NE + 255)/256;
    const int T1 = ((RR+1)*DD*DD + 255)/256;
    const int T2 = ((RR+1)*64*DD + 255)/256;
    k_pre    <<<HB + T1 + T2,    256>>>(edst, etyp, W1, r1, W2, r2);   // launch 0
    k_scan   <<<NBLK,           1024>>>();                              // launch 1
    k_scatter<<<(NE+255)/256,    256>>>(esrc, edst, etyp);              // launch 2

    k_layer<128,false><<<(NN+127)/128, 256, SMEM_L1>>>(x, w1h, b1, h);  // launch 3 (profiled)
    k_layer< 64,true ><<<(NN+127)/128, 256, SMEM_L2>>>(h, w2h, b2, out);// launch 4
}

// round 9
// speedup vs baseline: 1.1805x; 1.1805x over previous
#include <cuda_runtime.h>
#include <cuda_fp16.h>
#include <math.h>
#include <stdint.h>

#define NN 50000
#define NE 640000
#define RR 8
#define DD 128
#define NRSEG (NN*RR)
#define NBLK ((NRSEG + 1023)/1024)

// ---------------- scratch (device globals; no allocations allowed) ----------
__device__ int    g_cnt[NRSEG];          // zero at load; self-zeroed by k_scatter
__device__ int    g_off[NRSEG];
__device__ int    g_cur[NRSEG];
__device__ unsigned long long g_tstat[NBLK];  // lookback flags; reset by k_scatter
__device__ int2   g_sd[NE];              // (src, dst) packed, CSR order
__device__ float  g_h[NN*DD];
__device__ __half g_W1h[(RR+1)*DD*DD];   // [chunk][n][k-permuted] half
__device__ __half g_W2h[(RR+1)*64*DD];

// k-permutation within each 16-group: slot order packs (2t,2t+1,2t+8,2t+9)
// adjacent so one LDS.64 yields both fp16-MMA fragments.
__device__ __forceinline__ int slot16(int c) {
    return ((c & 7) >> 1)*4 + (c & 1) + ((c & 8) >> 3)*2;
}

// ---------------- prelude: hist + weight cvt/permute fused -------------------
// seg ordering is RELATION-MAJOR: seg = rel*NN + node, so each (warp-rows, rel)
// owns one contiguous edge slice sorted by dst.
__global__ void k_pre(const int* __restrict__ dst, const int* __restrict__ typ,
                      const float* __restrict__ W1, const float* __restrict__ r1,
                      const float* __restrict__ W2, const float* __restrict__ r2) {
    const int HB = (NE + 255)/256;
    const int T1 = ((RR+1)*DD*DD + 255)/256;
    int b = blockIdx.x;
    if (b < HB) {
        int e = b*256 + threadIdx.x;
        if (e < NE) atomicAdd(&g_cnt[typ[e]*NN + dst[e]], 1);
    } else if (b < HB + T1) {
        int idx = (b - HB)*256 + threadIdx.x;
        if (idx < (RR+1)*DD*DD) {
            int chunk = idx / (DD*DD);
            int rem   = idx - chunk*(DD*DD);
            int n = rem >> 7, k = rem & 127;
            float v = (chunk < RR) ? W1[(size_t)chunk*DD*DD + (size_t)k*DD + n]
                                   : r1[(size_t)k*DD + n];
            g_W1h[(size_t)chunk*DD*DD + n*DD + (k & ~15) + slot16(k & 15)] =
                __float2half_rn(v);
        }
    } else {
        int idx = (b - HB - T1)*256 + threadIdx.x;
        if (idx < (RR+1)*64*DD) {
            int chunk = idx / (64*DD);
            int rem   = idx - chunk*(64*DD);
            int n = rem >> 7, k = rem & 127;
            float v = (chunk < RR) ? W2[(size_t)chunk*DD*64 + (size_t)k*64 + n]
                                   : r2[(size_t)k*64 + n];
            g_W2h[(size_t)chunk*64*DD + n*DD + (k & ~15) + slot16(k & 15)] =
                __float2half_rn(v);
        }
    }
}

// ---------------- single-pass decoupled-lookback scan ------------------------
// flag: [63:32]=state (0=invalid,1=aggregate,2=prefix), [31:0]=value
__global__ void __launch_bounds__(1024)
k_scan() {
    __shared__ int swarp[32];
    __shared__ int s_prefix;
    const int tid  = threadIdx.x;
    const int lane = tid & 31;
    const int wid  = tid >> 5;
    const int b    = blockIdx.x;
    const int i    = b*1024 + tid;

    int v = (i < NRSEG) ? g_cnt[i] : 0;

    int x = v;
    #pragma unroll
    for (int d = 1; d < 32; d <<= 1) {
        int t = __shfl_up_sync(0xffffffffu, x, d);
        if (lane >= d) x += t;
    }
    if (lane == 31) swarp[wid] = x;
    __syncthreads();
    if (wid == 0) {
        int y = swarp[lane];
        #pragma unroll
        for (int d = 1; d < 32; d <<= 1) {
            int t = __shfl_up_sync(0xffffffffu, y, d);
            if (lane >= d) y += t;
        }
        swarp[lane] = y;
    }
    __syncthreads();
    int incl = x + ((wid > 0) ? swarp[wid-1] : 0);
    int blocksum = swarp[31];

    if (tid == 0) {
        if (b == 0) {
            atomicExch(&g_tstat[0], (2ULL<<32) | (unsigned)blocksum);
            s_prefix = 0;
        } else {
            atomicExch(&g_tstat[b], (1ULL<<32) | (unsigned)blocksum);
            int run = 0;
            int j = b - 1;
            while (true) {
                unsigned long long f = atomicAdd(&g_tstat[j], 0ULL);
                unsigned st = (unsigned)(f >> 32);
                if (st == 0) { __nanosleep(40); continue; }
                run += (int)(unsigned)(f & 0xffffffffu);
                if (st == 2) break;
                --j;
            }
            atomicExch(&g_tstat[b], (2ULL<<32) | (unsigned)(run + blocksum));
            s_prefix = run;
        }
    }
    __syncthreads();
    if (i < NRSEG) {
        int o = s_prefix + incl - v;
        g_off[i] = o;
        g_cur[i] = o;
    }
}

__global__ void k_scatter(const int* __restrict__ src, const int* __restrict__ dst,
                          const int* __restrict__ typ) {
    int e = blockIdx.x*blockDim.x + threadIdx.x;
    if (e < NE) {
        int d = dst[e];
        int seg = typ[e]*NN + d;
        int pos = atomicAdd(&g_cur[seg], 1);
        g_sd[pos] = make_int2(src[e], d);
    }
    // self-clean for next graph replay (unread after this point)
    if (e < NRSEG) g_cnt[e] = 0;
    if (e < NBLK)  g_tstat[e] = 0ULL;
}

// ---------------- fused aggregate + GEMM layer (fp16 MMA) -------------------
__device__ __forceinline__ void mma_f16(float& c0, float& c1, float& c2, float& c3,
                                        uint32_t a0, uint32_t a1, uint32_t a2, uint32_t a3,
                                        uint32_t b0, uint32_t b1) {
    asm volatile(
        "mma.sync.aligned.m16n8k16.row.col.f32.f16.f16.f32 "
        "{%0,%1,%2,%3},{%4,%5,%6,%7},{%8,%9},{%0,%1,%2,%3};"
        : "+f"(c0), "+f"(c1), "+f"(c2), "+f"(c3)
        : "r"(a0), "r"(a1), "r"(a2), "r"(a3), "r"(b0), "r"(b1));
}

__device__ __forceinline__ uint32_t pack_h2(float x, float y) {
    __half2 h = __floats2half2_rn(x, y);
    return *reinterpret_cast<uint32_t*>(&h);
}
__device__ __forceinline__ float2 unpack_h2(uint32_t u) {
    __half2 h = *reinterpret_cast<__half2*>(&u);
    return __half22float2(h);
}

// CTA = 128 nodes, 256 threads, 8 warps; warp owns 16 rows (private sA slice).
// Gather is two-level decoupled: one coalesced LDG.64 stages 32 edge records
// into lane registers; inner loop shfl-broadcasts them so the x-row gathers
// have register-resident addresses and pipeline at MLP 4-8.
template<int O, bool SIG>
__global__ void __launch_bounds__(256, 2)
k_layer(const float* __restrict__ in,
        const __half* __restrict__ Wh,    // [9][O][DD] half, k-permuted
        const float* __restrict__ bias,
        float* __restrict__ out) {
    constexpr int TM = 128;
    constexpr int NT = 256;
    constexpr int WP = 72;     // half2 words per row (64 data + 8 pad)

    extern __shared__ uint32_t smem[];
    uint32_t* sA = smem;           // TM * WP
    uint32_t* sB = smem + TM*WP;   // O  * WP

    const int tid  = threadIdx.x;
    const int lane = tid & 31;
    const int wid  = tid >> 5;
    const int tile = blockIdx.x * TM;

    float acc[O/8][4];
    #pragma unroll
    for (int n8 = 0; n8 < O/8; ++n8) {
        acc[n8][0] = 0.f; acc[n8][1] = 0.f; acc[n8][2] = 0.f; acc[n8][3] = 0.f;
    }

    const int g  = lane >> 2;
    const int tg = lane & 3;
    const int rbase = wid * 16;    // warp's private row block
    // lane's two half2 store slots (natural cols 4l..4l+3 under permutation)
    const int wbase = (lane >> 2)*8 + ((lane & 1) << 2) + ((lane & 2) >> 1);

    for (int r = 0; r < RR + 1; ++r) {
        __syncthreads();   // prev chunk's MMA done reading sB
        // ---- fill sB: pure half2 copy (pre-permuted in k_pre)
        {
            const uint32_t* Wp = reinterpret_cast<const uint32_t*>(
                Wh + (size_t)r*O*DD);
            #pragma unroll 4
            for (int idx = tid; idx < O*DD/2; idx += NT) {
                int n = idx >> 6, kk = idx & 63;
                sB[n*WP + kk] = Wp[idx];
            }
        }
        __syncthreads();   // sB ready

        // ================= gather (warp-private rows; no CTA barrier) ========
        if (r < RR) {
            // zero warp's 16 rows (contiguous block of 16*WP words)
            for (int w = lane; w < 16*WP; w += 32) sA[rbase*WP + w] = 0u;

            // lane l (l<=16) holds boundary offset for row rbase+l
            int bidx = r*NN + min(tile + rbase + min(lane, 16), NN);
            int offv = (bidx < NRSEG) ? g_off[bidx] : NE;
            int es = __shfl_sync(0xffffffffu, offv, 0);
            int ee = __shfl_sync(0xffffffffu, offv, 16);

            float4 v = make_float4(0.f,0.f,0.f,0.f);
            int currow = -1;
            for (int base = es; base < ee; base += 32) {
                const int m = min(ee - base, 32);
                // stage 32 edge records: ONE coalesced LDG.64 for the warp
                int2 sdl = make_int2(0, 0);
                if (lane < m) sdl = g_sd[base + lane];
                // inner loop: addresses via shfl (register-resident) -> MLP
                #pragma unroll 4
                for (int j = 0; j < m; ++j) {
                    int src = __shfl_sync(0xffffffffu, sdl.x, j);
                    int row = __shfl_sync(0xffffffffu, sdl.y, j);
                    const float4 xv = *reinterpret_cast<const float4*>(
                        in + (size_t)src*DD + (lane<<2));
                    bool fresh = (row != currow);
                    currow = row;
                    v.x = (fresh ? 0.f : v.x) + xv.x;
                    v.y = (fresh ? 0.f : v.y) + xv.y;
                    v.z = (fresh ? 0.f : v.z) + xv.z;
                    v.w = (fresh ? 0.f : v.w) + xv.w;
                    int rw = (currow - tile)*WP;
                    sA[rw + wbase]     = pack_h2(v.x, v.y);   // last write wins
                    sA[rw + wbase + 2] = pack_h2(v.z, v.w);
                }
            }

            // post-pass: scale rows by 1/cnt (thread-local slots)
            #pragma unroll
            for (int i = 0; i < 16; ++i) {
                int c = __shfl_sync(0xffffffffu, offv, i+1)
                      - __shfl_sync(0xffffffffu, offv, i);
                if (c > 0) {
                    float inv = 1.f/(float)c;
                    int idx = (rbase+i)*WP + wbase;
                    float2 u0 = unpack_h2(sA[idx]);
                    float2 u1 = unpack_h2(sA[idx+2]);
                    sA[idx]   = pack_h2(u0.x*inv, u0.y*inv);
                    sA[idx+2] = pack_h2(u1.x*inv, u1.y*inv);
                }
            }
        } else {
            // root chunk: direct copy of input tile
            #pragma unroll
            for (int ii = 0; ii < 16; ++ii) {
                int node = tile + rbase + ii;
                float4 xv = make_float4(0.f,0.f,0.f,0.f);
                if (node < NN)
                    xv = *reinterpret_cast<const float4*>(
                        in + (size_t)node*DD + (lane<<2));
                int idx = (rbase+ii)*WP + wbase;
                sA[idx]   = pack_h2(xv.x, xv.y);
                sA[idx+2] = pack_h2(xv.z, xv.w);
            }
        }
        __syncwarp();      // cross-lane sA reads in MMA below

        // ================= MMA (fp16, fp32 accum) =================
        #pragma unroll
        for (int k16 = 0; k16 < DD/16; ++k16) {
            const uint2 aLo = *reinterpret_cast<const uint2*>(
                &sA[(rbase + g    )*WP + k16*8 + tg*2]);   // (a0, a2)
            const uint2 aHi = *reinterpret_cast<const uint2*>(
                &sA[(rbase + g + 8)*WP + k16*8 + tg*2]);   // (a1, a3)
            #pragma unroll
            for (int n8 = 0; n8 < O/8; ++n8) {
                const uint2 bb = *reinterpret_cast<const uint2*>(
                    &sB[(n8*8 + g)*WP + k16*8 + tg*2]);    // (b0, b1)
                mma_f16(acc[n8][0], acc[n8][1], acc[n8][2], acc[n8][3],
                        aLo.x, aHi.x, aLo.y, aHi.y, bb.x, bb.y);
            }
        }
    }

    // ---- epilogue: bias (+ sigmoid), write out
    const int r0 = tile + rbase + g;
    const int r1 = r0 + 8;
    #pragma unroll
    for (int n8 = 0; n8 < O/8; ++n8) {
        int c0 = n8*8 + 2*tg;
        int c1 = c0 + 1;
        float bz0 = bias[c0], bz1 = bias[c1];
        float v00 = acc[n8][0] + bz0;
        float v01 = acc[n8][1] + bz1;
        float v10 = acc[n8][2] + bz0;
        float v11 = acc[n8][3] + bz1;
        if (SIG) {
            v00 = 1.f/(1.f + __expf(-v00));
            v01 = 1.f/(1.f + __expf(-v01));
            v10 = 1.f/(1.f + __expf(-v10));
            v11 = 1.f/(1.f + __expf(-v11));
        }
        if (r0 < NN) { out[(size_t)r0*O + c0] = v00; out[(size_t)r0*O + c1] = v01; }
        if (r1 < NN) { out[(size_t)r1*O + c0] = v10; out[(size_t)r1*O + c1] = v11; }
    }
}

// ---------------- launch ----------------------------------------------------
extern "C" void kernel_launch(void* const* d_in, const int* in_sizes, int n_in,
                              void* d_out, int out_size) {
    const float* x    = (const float*)d_in[0];
    const int*   esrc = (const int*)  d_in[1];
    const int*   edst = (const int*)  d_in[2];
    const int*   etyp = (const int*)  d_in[3];
    const float* W1   = (const float*)d_in[4];
    const float* r1   = (const float*)d_in[5];
    const float* b1   = (const float*)d_in[6];
    const float* W2   = (const float*)d_in[7];
    const float* r2   = (const float*)d_in[8];
    const float* b2   = (const float*)d_in[9];
    float* out = (float*)d_out;

    constexpr int SMEM_L1 = (128 + 128) * 72 * 4;  // 73728 B -> 2 CTAs/SM
    constexpr int SMEM_L2 = (128 +  64) * 72 * 4;  // 55296 B -> 2 CTAs/SM
    cudaFuncSetAttribute(k_layer<128,false>, cudaFuncAttributeMaxDynamicSharedMemorySize, SMEM_L1);
    cudaFuncSetAttribute(k_layer< 64,true >, cudaFuncAttributeMaxDynamicSharedMemorySize, SMEM_L2);

    void* p = nullptr;
    cudaGetSymbolAddress(&p, g_h);   float*  h   = (float*)p;
    cudaGetSymbolAddress(&p, g_W1h); __half* w1h = (__half*)p;
    cudaGetSymbolAddress(&p, g_W2h); __half* w2h = (__half*)p;

    const int HB = (NE + 255)/256;
    const int T1 = ((RR+1)*DD*DD + 255)/256;
    const int T2 = ((RR+1)*64*DD + 255)/256;
    k_pre    <<<HB + T1 + T2,    256>>>(edst, etyp, W1, r1, W2, r2);   // launch 0
    k_scan   <<<NBLK,           1024>>>();                              // launch 1
    k_scatter<<<(NE+255)/256,    256>>>(esrc, edst, etyp);              // launch 2

    k_layer<128,false><<<(NN+127)/128, 256, SMEM_L1>>>(x, w1h, b1, h);  // launch 3 (profiled)
    k_layer< 64,true ><<<(NN+127)/128, 256, SMEM_L2>>>(h, w2h, b2, out);// launch 4
}

// round 10
// speedup vs baseline: 1.4136x; 1.1975x over previous
#include <cuda_runtime.h>
#include <cuda_fp16.h>
#include <math.h>
#include <stdint.h>

#define NN 50000
#define NE 640000
#define RR 8
#define DD 128
#define NRSEG (NN*RR)
#define NBLK ((NRSEG + 1023)/1024)

// ---------------- scratch (device globals; no allocations allowed) ----------
__device__ int    g_cnt[NRSEG];          // zero at load; self-zeroed by k_scatter
__device__ int    g_off[NRSEG];
__device__ int    g_cur[NRSEG];
__device__ unsigned long long g_tstat[NBLK];  // lookback flags; reset by k_scatter
__device__ int2   g_sd[NE];              // (src, dst) packed, CSR order
__device__ float  g_h[NN*DD];
__device__ __half g_W1h[(RR+1)*DD*DD];   // [chunk][n][k-permuted] half
__device__ __half g_W2h[(RR+1)*64*DD];

// k-permutation within each 16-group: slot order packs (2t,2t+1,2t+8,2t+9)
// adjacent so one LDS.64 yields both fp16-MMA fragments.
__device__ __forceinline__ int slot16(int c) {
    return ((c & 7) >> 1)*4 + (c & 1) + ((c & 8) >> 3)*2;
}

// ---------------- prelude: hist + weight cvt/permute fused -------------------
// seg ordering is RELATION-MAJOR: seg = rel*NN + node, so each row-block x rel
// owns one contiguous edge slice sorted by dst.
__global__ void k_pre(const int* __restrict__ dst, const int* __restrict__ typ,
                      const float* __restrict__ W1, const float* __restrict__ r1,
                      const float* __restrict__ W2, const float* __restrict__ r2) {
    const int HB = (NE + 255)/256;
    const int T1 = ((RR+1)*DD*DD + 255)/256;
    int b = blockIdx.x;
    if (b < HB) {
        int e = b*256 + threadIdx.x;
        if (e < NE) atomicAdd(&g_cnt[typ[e]*NN + dst[e]], 1);
    } else if (b < HB + T1) {
        int idx = (b - HB)*256 + threadIdx.x;
        if (idx < (RR+1)*DD*DD) {
            int chunk = idx / (DD*DD);
            int rem   = idx - chunk*(DD*DD);
            int n = rem >> 7, k = rem & 127;
            float v = (chunk < RR) ? W1[(size_t)chunk*DD*DD + (size_t)k*DD + n]
                                   : r1[(size_t)k*DD + n];
            g_W1h[(size_t)chunk*DD*DD + n*DD + (k & ~15) + slot16(k & 15)] =
                __float2half_rn(v);
        }
    } else {
        int idx = (b - HB - T1)*256 + threadIdx.x;
        if (idx < (RR+1)*64*DD) {
            int chunk = idx / (64*DD);
            int rem   = idx - chunk*(64*DD);
            int n = rem >> 7, k = rem & 127;
            float v = (chunk < RR) ? W2[(size_t)chunk*DD*64 + (size_t)k*64 + n]
                                   : r2[(size_t)k*64 + n];
            g_W2h[(size_t)chunk*64*DD + n*DD + (k & ~15) + slot16(k & 15)] =
                __float2half_rn(v);
        }
    }
}

// ---------------- single-pass decoupled-lookback scan ------------------------
__global__ void __launch_bounds__(1024)
k_scan() {
    __shared__ int swarp[32];
    __shared__ int s_prefix;
    const int tid  = threadIdx.x;
    const int lane = tid & 31;
    const int wid  = tid >> 5;
    const int b    = blockIdx.x;
    const int i    = b*1024 + tid;

    int v = (i < NRSEG) ? g_cnt[i] : 0;

    int x = v;
    #pragma unroll
    for (int d = 1; d < 32; d <<= 1) {
        int t = __shfl_up_sync(0xffffffffu, x, d);
        if (lane >= d) x += t;
    }
    if (lane == 31) swarp[wid] = x;
    __syncthreads();
    if (wid == 0) {
        int y = swarp[lane];
        #pragma unroll
        for (int d = 1; d < 32; d <<= 1) {
            int t = __shfl_up_sync(0xffffffffu, y, d);
            if (lane >= d) y += t;
        }
        swarp[lane] = y;
    }
    __syncthreads();
    int incl = x + ((wid > 0) ? swarp[wid-1] : 0);
    int blocksum = swarp[31];

    if (tid == 0) {
        if (b == 0) {
            atomicExch(&g_tstat[0], (2ULL<<32) | (unsigned)blocksum);
            s_prefix = 0;
        } else {
            atomicExch(&g_tstat[b], (1ULL<<32) | (unsigned)blocksum);
            int run = 0;
            int j = b - 1;
            while (true) {
                unsigned long long f = atomicAdd(&g_tstat[j], 0ULL);
                unsigned st = (unsigned)(f >> 32);
                if (st == 0) { __nanosleep(40); continue; }
                run += (int)(unsigned)(f & 0xffffffffu);
                if (st == 2) break;
                --j;
            }
            atomicExch(&g_tstat[b], (2ULL<<32) | (unsigned)(run + blocksum));
            s_prefix = run;
        }
    }
    __syncthreads();
    if (i < NRSEG) {
        int o = s_prefix + incl - v;
        g_off[i] = o;
        g_cur[i] = o;
    }
}

__global__ void k_scatter(const int* __restrict__ src, const int* __restrict__ dst,
                          const int* __restrict__ typ) {
    int e = blockIdx.x*blockDim.x + threadIdx.x;
    if (e < NE) {
        int d = dst[e];
        int seg = typ[e]*NN + d;
        int pos = atomicAdd(&g_cur[seg], 1);
        g_sd[pos] = make_int2(src[e], d);
    }
    if (e < NRSEG) g_cnt[e] = 0;
    if (e < NBLK)  g_tstat[e] = 0ULL;
}

// ---------------- fused aggregate + GEMM layer (fp16 MMA) -------------------
__device__ __forceinline__ void mma_f16(float& c0, float& c1, float& c2, float& c3,
                                        uint32_t a0, uint32_t a1, uint32_t a2, uint32_t a3,
                                        uint32_t b0, uint32_t b1) {
    asm volatile(
        "mma.sync.aligned.m16n8k16.row.col.f32.f16.f16.f32 "
        "{%0,%1,%2,%3},{%4,%5,%6,%7},{%8,%9},{%0,%1,%2,%3};"
        : "+f"(c0), "+f"(c1), "+f"(c2), "+f"(c3)
        : "r"(a0), "r"(a1), "r"(a2), "r"(a3), "r"(b0), "r"(b1));
}

__device__ __forceinline__ uint32_t pack_h2(float x, float y) {
    __half2 h = __floats2half2_rn(x, y);
    return *reinterpret_cast<uint32_t*>(&h);
}
__device__ __forceinline__ float2 unpack_h2(uint32_t u) {
    __half2 h = *reinterpret_cast<__half2*>(&u);
    return __half22float2(h);
}

// CTA = 128 nodes, 512 threads, 16 warps, 2 CTAs/SM (32 warps/SM, occ 50%).
// Gather: warp w gathers rows [8w, 8w+8) (staged shfl gather, MLP 4-8).
// MMA:    warp w computes rows [16*(w&7), +16) x cols [(w>>3)*O/2, +O/2)
//         -> acc 32 regs (O=128) so 2 CTAs fit the register file.
template<int O, bool SIG>
__global__ void __launch_bounds__(512, 2)
k_layer(const float* __restrict__ in,
        const __half* __restrict__ Wh,    // [9][O][DD] half, k-permuted
        const float* __restrict__ bias,
        float* __restrict__ out) {
    constexpr int TM = 128;
    constexpr int NT = 512;
    constexpr int WP = 72;     // half2 words per row (64 data + 8 pad)
    constexpr int O2 = O/2;

    extern __shared__ uint32_t smem[];
    uint32_t* sA = smem;           // TM * WP
    uint32_t* sB = smem + TM*WP;   // O  * WP

    const int tid  = threadIdx.x;
    const int lane = tid & 31;
    const int wid  = tid >> 5;
    const int tile = blockIdx.x * TM;

    float acc[O2/8][4];
    #pragma unroll
    for (int n8 = 0; n8 < O2/8; ++n8) {
        acc[n8][0] = 0.f; acc[n8][1] = 0.f; acc[n8][2] = 0.f; acc[n8][3] = 0.f;
    }

    const int g  = lane >> 2;
    const int tg = lane & 3;
    const int mrow = (wid & 7) * 16;   // MMA row block
    const int ncol = (wid >> 3) * O2;  // MMA col block (sB row offset)
    const int grow = wid * 8;          // gather row block (8 rows)
    // lane's two half2 store slots (natural cols 4l..4l+3 under permutation)
    const int wbase = (lane >> 2)*8 + ((lane & 1) << 2) + ((lane & 2) >> 1);

    for (int r = 0; r < RR + 1; ++r) {
        __syncthreads();   // prev chunk's MMA done reading sA/sB
        // ---- fill sB: pure half2 copy (pre-permuted in k_pre)
        {
            const uint32_t* Wp = reinterpret_cast<const uint32_t*>(
                Wh + (size_t)r*O*DD);
            #pragma unroll 4
            for (int idx = tid; idx < O*DD/2; idx += NT) {
                int n = idx >> 6, kk = idx & 63;
                sB[n*WP + kk] = Wp[idx];
            }
        }
        __syncthreads();   // sB ready; prev MMA reads of sA drained

        // ================= gather: warp -> 8 rows =================
        if (r < RR) {
            // zero warp's 8 rows
            for (int w = lane; w < 8*WP; w += 32) sA[grow*WP + w] = 0u;

            // lane l (l<=8) holds boundary offset for row grow+l
            int bidx = r*NN + min(tile + grow + min(lane, 8), NN);
            int offv = (bidx < NRSEG) ? g_off[bidx] : NE;
            int es = __shfl_sync(0xffffffffu, offv, 0);
            int ee = __shfl_sync(0xffffffffu, offv, 8);

            float4 v = make_float4(0.f,0.f,0.f,0.f);
            int currow = -1;
            for (int base = es; base < ee; base += 32) {
                const int m = min(ee - base, 32);
                // stage edge records: ONE coalesced LDG.64 for the warp
                int2 sdl = make_int2(0, 0);
                if (lane < m) sdl = g_sd[base + lane];
                // inner loop: addresses via shfl (register-resident) -> MLP
                #pragma unroll 4
                for (int j = 0; j < m; ++j) {
                    int src = __shfl_sync(0xffffffffu, sdl.x, j);
                    int row = __shfl_sync(0xffffffffu, sdl.y, j);
                    const float4 xv = *reinterpret_cast<const float4*>(
                        in + (size_t)src*DD + (lane<<2));
                    bool fresh = (row != currow);
                    currow = row;
                    v.x = (fresh ? 0.f : v.x) + xv.x;
                    v.y = (fresh ? 0.f : v.y) + xv.y;
                    v.z = (fresh ? 0.f : v.z) + xv.z;
                    v.w = (fresh ? 0.f : v.w) + xv.w;
                    int rw = (currow - tile)*WP;
                    sA[rw + wbase]     = pack_h2(v.x, v.y);   // last write wins
                    sA[rw + wbase + 2] = pack_h2(v.z, v.w);
                }
            }

            // post-pass: scale rows by 1/cnt (thread-local slots)
            #pragma unroll
            for (int i = 0; i < 8; ++i) {
                int c = __shfl_sync(0xffffffffu, offv, i+1)
                      - __shfl_sync(0xffffffffu, offv, i);
                if (c > 0) {
                    float inv = 1.f/(float)c;
                    int idx = (grow+i)*WP + wbase;
                    float2 u0 = unpack_h2(sA[idx]);
                    float2 u1 = unpack_h2(sA[idx+2]);
                    sA[idx]   = pack_h2(u0.x*inv, u0.y*inv);
                    sA[idx+2] = pack_h2(u1.x*inv, u1.y*inv);
                }
            }
        } else {
            // root chunk: direct copy of input tile
            #pragma unroll
            for (int ii = 0; ii < 8; ++ii) {
                int node = tile + grow + ii;
                float4 xv = make_float4(0.f,0.f,0.f,0.f);
                if (node < NN)
                    xv = *reinterpret_cast<const float4*>(
                        in + (size_t)node*DD + (lane<<2));
                int idx = (grow+ii)*WP + wbase;
                sA[idx]   = pack_h2(xv.x, xv.y);
                sA[idx+2] = pack_h2(xv.z, xv.w);
            }
        }
        __syncthreads();   // sA tile complete (cross-warp rows)

        // ================= MMA (fp16, fp32 accum) =================
        #pragma unroll
        for (int k16 = 0; k16 < DD/16; ++k16) {
            const uint2 aLo = *reinterpret_cast<const uint2*>(
                &sA[(mrow + g    )*WP + k16*8 + tg*2]);   // (a0, a2)
            const uint2 aHi = *reinterpret_cast<const uint2*>(
                &sA[(mrow + g + 8)*WP + k16*8 + tg*2]);   // (a1, a3)
            #pragma unroll
            for (int n8 = 0; n8 < O2/8; ++n8) {
                const uint2 bb = *reinterpret_cast<const uint2*>(
                    &sB[(ncol + n8*8 + g)*WP + k16*8 + tg*2]);  // (b0, b1)
                mma_f16(acc[n8][0], acc[n8][1], acc[n8][2], acc[n8][3],
                        aLo.x, aHi.x, aLo.y, aHi.y, bb.x, bb.y);
            }
        }
    }

    // ---- epilogue: bias (+ sigmoid), write out
    const int r0 = tile + mrow + g;
    const int r1 = r0 + 8;
    #pragma unroll
    for (int n8 = 0; n8 < O2/8; ++n8) {
        int c0 = ncol + n8*8 + 2*tg;
        int c1 = c0 + 1;
        float bz0 = bias[c0], bz1 = bias[c1];
        float v00 = acc[n8][0] + bz0;
        float v01 = acc[n8][1] + bz1;
        float v10 = acc[n8][2] + bz0;
        float v11 = acc[n8][3] + bz1;
        if (SIG) {
            v00 = 1.f/(1.f + __expf(-v00));
            v01 = 1.f/(1.f + __expf(-v01));
            v10 = 1.f/(1.f + __expf(-v10));
            v11 = 1.f/(1.f + __expf(-v11));
        }
        if (r0 < NN) { out[(size_t)r0*O + c0] = v00; out[(size_t)r0*O + c1] = v01; }
        if (r1 < NN) { out[(size_t)r1*O + c0] = v10; out[(size_t)r1*O + c1] = v11; }
    }
}

// ---------------- launch ----------------------------------------------------
extern "C" void kernel_launch(void* const* d_in, const int* in_sizes, int n_in,
                              void* d_out, int out_size) {
    const float* x    = (const float*)d_in[0];
    const int*   esrc = (const int*)  d_in[1];
    const int*   edst = (const int*)  d_in[2];
    const int*   etyp = (const int*)  d_in[3];
    const float* W1   = (const float*)d_in[4];
    const float* r1   = (const float*)d_in[5];
    const float* b1   = (const float*)d_in[6];
    const float* W2   = (const float*)d_in[7];
    const float* r2   = (const float*)d_in[8];
    const float* b2   = (const float*)d_in[9];
    float* out = (float*)d_out;

    constexpr int SMEM_L1 = (128 + 128) * 72 * 4;  // 73728 B -> 2 CTAs/SM
    constexpr int SMEM_L2 = (128 +  64) * 72 * 4;  // 55296 B -> 2 CTAs/SM
    cudaFuncSetAttribute(k_layer<128,false>, cudaFuncAttributeMaxDynamicSharedMemorySize, SMEM_L1);
    cudaFuncSetAttribute(k_layer< 64,true >, cudaFuncAttributeMaxDynamicSharedMemorySize, SMEM_L2);

    void* p = nullptr;
    cudaGetSymbolAddress(&p, g_h);   float*  h   = (float*)p;
    cudaGetSymbolAddress(&p, g_W1h); __half* w1h = (__half*)p;
    cudaGetSymbolAddress(&p, g_W2h); __half* w2h = (__half*)p;

    const int HB = (NE + 255)/256;
    const int T1 = ((RR+1)*DD*DD + 255)/256;
    const int T2 = ((RR+1)*64*DD + 255)/256;
    k_pre    <<<HB + T1 + T2,    256>>>(edst, etyp, W1, r1, W2, r2);   // launch 0
    k_scan   <<<NBLK,           1024>>>();                              // launch 1
    k_scatter<<<(NE+255)/256,    256>>>(esrc, edst, etyp);              // launch 2

    k_layer<128,false><<<(NN+127)/128, 512, SMEM_L1>>>(x, w1h, b1, h);  // launch 3 (profiled)
    k_layer< 64,true ><<<(NN+127)/128, 512, SMEM_L2>>>(h, w2h, b2, out);// launch 4
}